// round 10
// baseline (speedup 1.0000x reference)
#include <cuda_runtime.h>

// ov[b*256 + c] as float4s; flags for single-kernel producer/consumer sync.
__device__ __align__(16) float d_ov[8 * 256];
__device__ int g_ready;   // zero-initialized; reset by last block each launch
__device__ int g_done;

#define EPSF 1e-5f

// 512 blocks x 256 threads.
// Blocks 0..7: compute ov for batch b = blockIdx.x, publish, then do their img slice.
// Blocks 8..511: front-batch img loads (overlaps ov compute), spin on flag, add, store.
__global__ void __launch_bounds__(256, 4)
fused_kernel(const float4* __restrict__ img,              // (8,1024,256) as float4
             const float*  __restrict__ param_tokens,     // (8,16)
             const float*  __restrict__ Wparam,           // (16,256)
             const float*  __restrict__ bparam,           // (256)
             const float*  __restrict__ ctx_g,            // (256)
             const float*  __restrict__ ctx_b,            // (256)
             const float4* __restrict__ Wkv4,             // (256,512) as float4: [i*128 + j]
             const float4* __restrict__ Wout4,            // (256,256) as float4: [i*64 + j]
             const float4* __restrict__ bout4,            // (256) as float4
             float4* __restrict__ out)                    // (8,1024,256) as float4
{
    const int bid = blockIdx.x;
    const int tid = threadIdx.x;
    const int t   = bid * 256 + tid;       // global float4 index base, 0..131071
    const int c4  = t & 63;                // float4 index within channel dim
    const int b0  = t >> 16;               // 0 or 1
    const float4* ovp = reinterpret_cast<const float4*>(d_ov);

    __shared__ float  s_ln[256];
    __shared__ float  s_v[256];
    __shared__ float4 s_part[256];
    __shared__ float  s_red[16];

    float4 a0, a1, a2, a3;
    bool loaded = false;

    if (bid < 8) {
        // ================= compute ov for batch b = bid =================
        const int b = bid;
        const int c = tid;

        // ---- ctx[c] = param_tokens[b] @ Wparam + bparam ----
        float ctx = bparam[c];
        const float* pt = param_tokens + b * 16;
#pragma unroll
        for (int p = 0; p < 16; ++p)
            ctx = fmaf(__ldg(&pt[p]), Wparam[p * 256 + c], ctx);

        // ---- layernorm stats (block reduce over 256) ----
        float ss = ctx, qq = ctx * ctx;
#pragma unroll
        for (int o = 16; o > 0; o >>= 1) {
            ss += __shfl_down_sync(0xffffffffu, ss, o);
            qq += __shfl_down_sync(0xffffffffu, qq, o);
        }
        const int warp = tid >> 5, lane = tid & 31;
        if (lane == 0) { s_red[warp] = ss; s_red[8 + warp] = qq; }
        __syncthreads();
        if (tid < 32) {
            float s2 = (tid < 8) ? s_red[tid]     : 0.0f;
            float q2 = (tid < 8) ? s_red[8 + tid] : 0.0f;
#pragma unroll
            for (int o = 4; o > 0; o >>= 1) {
                s2 += __shfl_down_sync(0xffffffffu, s2, o);
                q2 += __shfl_down_sync(0xffffffffu, q2, o);
            }
            if (tid == 0) { s_red[0] = s2; s_red[1] = q2; }
        }
        __syncthreads();
        const float mean = s_red[0] * (1.0f / 256.0f);
        const float var  = s_red[1] * (1.0f / 256.0f) - mean * mean;
        const float rinv = rsqrtf(var + EPSF);
        s_ln[c] = fmaf((ctx - mean) * rinv, ctx_g[c], ctx_b[c]);
        __syncthreads();

        // ---- GEMV1: v = ln @ Wkv[:,256:512], float4 along channels ----
        // thread: cj = tid & 63 (4 channels), ks = tid >> 6 (k-slice of 64)
        const int cj = tid & 63;
        const int kb = (tid >> 6) * 64;
        {
            float4 acc = make_float4(0.f, 0.f, 0.f, 0.f);
#pragma unroll
            for (int i = 0; i < 64; ++i) {
                const float  f = s_ln[kb + i];
                const float4 w = Wkv4[(kb + i) * 128 + 64 + cj];
                acc.x = fmaf(f, w.x, acc.x);
                acc.y = fmaf(f, w.y, acc.y);
                acc.z = fmaf(f, w.z, acc.z);
                acc.w = fmaf(f, w.w, acc.w);
            }
            s_part[tid] = acc;
        }
        __syncthreads();
        if (tid < 64) {
            const float4 p0 = s_part[tid], p1 = s_part[64 + tid];
            const float4 p2 = s_part[128 + tid], p3 = s_part[192 + tid];
            s_v[4 * tid + 0] = (p0.x + p1.x) + (p2.x + p3.x);
            s_v[4 * tid + 1] = (p0.y + p1.y) + (p2.y + p3.y);
            s_v[4 * tid + 2] = (p0.z + p1.z) + (p2.z + p3.z);
            s_v[4 * tid + 3] = (p0.w + p1.w) + (p2.w + p3.w);
        }
        __syncthreads();

        // ---- GEMV2: ov = v @ Wout + bout ----
        {
            float4 acc = make_float4(0.f, 0.f, 0.f, 0.f);
#pragma unroll
            for (int i = 0; i < 64; ++i) {
                const float  f = s_v[kb + i];
                const float4 w = Wout4[(kb + i) * 64 + cj];
                acc.x = fmaf(f, w.x, acc.x);
                acc.y = fmaf(f, w.y, acc.y);
                acc.z = fmaf(f, w.z, acc.z);
                acc.w = fmaf(f, w.w, acc.w);
            }
            s_part[tid] = acc;
        }
        __syncthreads();
        if (tid < 64) {
            const float4 p0 = s_part[tid], p1 = s_part[64 + tid];
            const float4 p2 = s_part[128 + tid], p3 = s_part[192 + tid];
            const float4 bo = bout4[tid];
            float4 o;
            o.x = bo.x + (p0.x + p1.x) + (p2.x + p3.x);
            o.y = bo.y + (p0.y + p1.y) + (p2.y + p3.y);
            o.z = bo.z + (p0.z + p1.z) + (p2.z + p3.z);
            o.w = bo.w + (p0.w + p1.w) + (p2.w + p3.w);
            reinterpret_cast<float4*>(d_ov)[b * 64 + tid] = o;
        }
        __syncthreads();                 // all d_ov writes done block-wide
        if (tid == 0) {
            __threadfence();             // make d_ov visible device-wide
            atomicAdd(&g_ready, 1);
        }
    } else {
        // ============ front-batch img loads: overlap with ov compute ============
        a0 = img[t];
        a1 = img[t + 131072];
        a2 = img[t + 262144];
        a3 = img[t + 393216];
        loaded = true;
    }

    // ---- wait until all 8 ov batches are published ----
    if (tid == 0) {
        volatile int* r = &g_ready;
        while (*r < 8) __nanosleep(64);
        __threadfence();                 // acquire: order d_ov reads after flag
    }
    __syncthreads();

    if (!loaded) {                       // compute blocks load their img slice now
        a0 = img[t];
        a1 = img[t + 131072];
        a2 = img[t + 262144];
        a3 = img[t + 393216];
    }

    const float4 o0 = ovp[(b0 + 0) * 64 + c4];
    const float4 o1 = ovp[(b0 + 2) * 64 + c4];
    const float4 o2 = ovp[(b0 + 4) * 64 + c4];
    const float4 o3 = ovp[(b0 + 6) * 64 + c4];

    out[t]          = make_float4(a0.x + o0.x, a0.y + o0.y, a0.z + o0.z, a0.w + o0.w);
    out[t + 131072] = make_float4(a1.x + o1.x, a1.y + o1.y, a1.z + o1.z, a1.w + o1.w);
    out[t + 262144] = make_float4(a2.x + o2.x, a2.y + o2.y, a2.z + o2.z, a2.w + o2.w);
    out[t + 393216] = make_float4(a3.x + o3.x, a3.y + o3.y, a3.z + o3.z, a3.w + o3.w);

    // ---- reset flags for the next graph replay (last block to finish) ----
    __syncthreads();
    if (tid == 0) {
        __threadfence();
        const int d = atomicAdd(&g_done, 1);
        if (d == 511) { g_done = 0; g_ready = 0; __threadfence(); }
    }
}

extern "C" void kernel_launch(void* const* d_in, const int* in_sizes, int n_in,
                              void* d_out, int out_size)
{
    // metadata order:
    // 0 img_tokens (8,1024,256)  1 param_tokens (8,16)
    // 2 img_norm_g 3 img_norm_b  4 Wq            <- all dead (softmax collapse)
    // 5 Wparam (16,256)  6 bparam (256)
    // 7 ctx_norm_g (256) 8 ctx_norm_b (256)
    // 9 Wkv (256,512)   10 Wout (256,256)  11 bout (256)
    const float* img          = (const float*)d_in[0];
    const float* param_tokens = (const float*)d_in[1];
    const float* Wparam       = (const float*)d_in[5];
    const float* bparam       = (const float*)d_in[6];
    const float* ctx_g        = (const float*)d_in[7];
    const float* ctx_b        = (const float*)d_in[8];
    const float* Wkv          = (const float*)d_in[9];
    const float* Wout         = (const float*)d_in[10];
    const float* bout         = (const float*)d_in[11];
    float* out = (float*)d_out;

    fused_kernel<<<512, 256>>>((const float4*)img, param_tokens, Wparam, bparam,
                               ctx_g, ctx_b,
                               (const float4*)Wkv, (const float4*)Wout,
                               (const float4*)bout, (float4*)out);
}

// round 12
// speedup vs baseline: 1.1057x; 1.1057x over previous
#include <cuda_runtime.h>

// d_ov[b*256 + c], 16B-aligned for float4 reads in the broadcast kernel.
__device__ __align__(16) float d_ov[8 * 256];

#define EPSF 1e-5f

// One block per batch row b (8 blocks, 1024 threads).
// Thread t handles output channel c = t & 255, k-slice s = t >> 8 (4-way split
// of the 256-deep dot products -> 64 MACs per thread, fully unrolled).
__global__ void __launch_bounds__(1024, 1)
compute_ov_kernel(const float* __restrict__ param_tokens,  // (8,16)
                  const float* __restrict__ Wparam,        // (16,256)
                  const float* __restrict__ bparam,        // (256)
                  const float* __restrict__ ctx_g,         // (256)
                  const float* __restrict__ ctx_b,         // (256)
                  const float* __restrict__ Wkv,           // (256,512)
                  const float* __restrict__ Wout,          // (256,256)
                  const float* __restrict__ bout)          // (256)
{
    // Allow the dependent (broadcast) grid to launch right away: its img
    // loads stream in while we compute ov. Visibility of d_ov for the
    // dependent grid is guaranteed by its griddepcontrol.wait.
    asm volatile("griddepcontrol.launch_dependents;");

    const int b   = blockIdx.x;
    const int tid = threadIdx.x;
    const int c   = tid & 255;
    const int s   = tid >> 8;          // 0..3
    const int kb  = s * 64;            // this thread's k-base

    __shared__ float s_ln[256];
    __shared__ float s_v[256];
    __shared__ float s_part[4 * 256];
    __shared__ float s_red[16];

    // Weight column pointers (coalesced across c). Independent of LN result,
    // so prefetch the first 16 GEMV-1 weights NOW — they land while the
    // ctx/layernorm phase runs, hiding the first DRAM latency.
    const float* wk = Wkv  + 256 + c + kb * 512;   // V-half column c, stride 512
    const float* wo = Wout + c       + kb * 256;   // Wout column c, stride 256

    float wpre[16];
#pragma unroll
    for (int i = 0; i < 16; ++i) wpre[i] = wk[i * 512];

    // ---- ctx[c] (s==0 threads only) + LN stats ----
    float ctx = 0.0f;
    if (s == 0) {
        ctx = bparam[c];
        const float* pt = param_tokens + b * 16;
#pragma unroll
        for (int p = 0; p < 16; ++p)
            ctx = fmaf(__ldg(&pt[p]), Wparam[p * 256 + c], ctx);

        float ss = ctx, qq = ctx * ctx;
#pragma unroll
        for (int o = 16; o > 0; o >>= 1) {
            ss += __shfl_down_sync(0xffffffffu, ss, o);
            qq += __shfl_down_sync(0xffffffffu, qq, o);
        }
        const int warp = tid >> 5, lane = tid & 31;   // warps 0..7
        if (lane == 0) { s_red[warp] = ss; s_red[8 + warp] = qq; }
    }
    __syncthreads();
    if (tid < 32) {
        float ss = (tid < 8) ? s_red[tid]     : 0.0f;
        float qq = (tid < 8) ? s_red[8 + tid] : 0.0f;
#pragma unroll
        for (int o = 4; o > 0; o >>= 1) {
            ss += __shfl_down_sync(0xffffffffu, ss, o);
            qq += __shfl_down_sync(0xffffffffu, qq, o);
        }
        if (tid == 0) { s_red[0] = ss; s_red[1] = qq; }
    }
    __syncthreads();
    if (s == 0) {
        const float mean = s_red[0] * (1.0f / 256.0f);
        const float var  = s_red[1] * (1.0f / 256.0f) - mean * mean;
        const float rinv = rsqrtf(var + EPSF);
        s_ln[c] = fmaf((ctx - mean) * rinv, ctx_g[c], ctx_b[c]);
    }
    __syncthreads();

    // ---- GEMV1 partial: v_part = sum_{i in slice} ln[kb+i] * Wkv_V[kb+i][c] ----
    {
        float a0 = 0.f, a1 = 0.f, a2 = 0.f, a3 = 0.f;
#pragma unroll
        for (int i = 0; i < 16; ++i) {
            float acc = fmaf(s_ln[kb + i], wpre[i], 0.0f);
            if ((i & 3) == 0) a0 += acc; else if ((i & 3) == 1) a1 += acc;
            else if ((i & 3) == 2) a2 += acc; else a3 += acc;
        }
#pragma unroll
        for (int i = 16; i < 64; i += 4) {
            a0 = fmaf(s_ln[kb + i + 0], wk[(i + 0) * 512], a0);
            a1 = fmaf(s_ln[kb + i + 1], wk[(i + 1) * 512], a1);
            a2 = fmaf(s_ln[kb + i + 2], wk[(i + 2) * 512], a2);
            a3 = fmaf(s_ln[kb + i + 3], wk[(i + 3) * 512], a3);
        }
        s_part[tid] = (a0 + a1) + (a2 + a3);
    }
    __syncthreads();
    if (s == 0)
        s_v[c] = s_part[c] + s_part[256 + c] + s_part[512 + c] + s_part[768 + c];
    __syncthreads();

    // ---- GEMV2 partial: ov_part = sum_{i in slice} v[kb+i] * Wout[kb+i][c] ----
    {
        float a0 = 0.f, a1 = 0.f, a2 = 0.f, a3 = 0.f;
#pragma unroll
        for (int i = 0; i < 64; i += 4) {
            a0 = fmaf(s_v[kb + i + 0], wo[(i + 0) * 256], a0);
            a1 = fmaf(s_v[kb + i + 1], wo[(i + 1) * 256], a1);
            a2 = fmaf(s_v[kb + i + 2], wo[(i + 2) * 256], a2);
            a3 = fmaf(s_v[kb + i + 3], wo[(i + 3) * 256], a3);
        }
        s_part[tid] = (a0 + a1) + (a2 + a3);
    }
    __syncthreads();
    if (s == 0)
        d_ov[b * 256 + c] = bout[c] + s_part[c] + s_part[256 + c]
                          + s_part[512 + c] + s_part[768 + c];
}

// out[b,n,c] = img[b,n,c] + ov[b,c].
// 512 blocks x 256 threads; each thread handles 4 float4s strided by 131072.
// Launched with ProgrammaticStreamSerialization: starts while compute_ov runs,
// front-batches its img loads, then griddepcontrol.wait gates the ov reads.
__global__ void __launch_bounds__(256, 8)
broadcast_add_kernel(const float4* __restrict__ img, float4* __restrict__ out)
{
    const int t  = blockIdx.x * 256 + threadIdx.x;   // 0..131071
    const int c4 = t & 63;
    const int b0 = t >> 16;                          // 0 or 1
    const float4* ovp = reinterpret_cast<const float4*>(d_ov);

    // front-batched loads — overlap with compute_ov under PDL
    const float4 a0 = img[t];
    const float4 a1 = img[t + 131072];
    const float4 a2 = img[t + 262144];
    const float4 a3 = img[t + 393216];

    // HW wait: primary grid complete + its writes (d_ov) visible.
    asm volatile("griddepcontrol.wait;");

    const float4 o0 = ovp[(b0 + 0) * 64 + c4];
    const float4 o1 = ovp[(b0 + 2) * 64 + c4];
    const float4 o2 = ovp[(b0 + 4) * 64 + c4];
    const float4 o3 = ovp[(b0 + 6) * 64 + c4];

    out[t]          = make_float4(a0.x + o0.x, a0.y + o0.y, a0.z + o0.z, a0.w + o0.w);
    out[t + 131072] = make_float4(a1.x + o1.x, a1.y + o1.y, a1.z + o1.z, a1.w + o1.w);
    out[t + 262144] = make_float4(a2.x + o2.x, a2.y + o2.y, a2.z + o2.z, a2.w + o2.w);
    out[t + 393216] = make_float4(a3.x + o3.x, a3.y + o3.y, a3.z + o3.z, a3.w + o3.w);
}

extern "C" void kernel_launch(void* const* d_in, const int* in_sizes, int n_in,
                              void* d_out, int out_size)
{
    // metadata order:
    // 0 img_tokens (8,1024,256)  1 param_tokens (8,16)
    // 2 img_norm_g 3 img_norm_b  4 Wq            <- all dead (softmax collapse)
    // 5 Wparam (16,256)  6 bparam (256)
    // 7 ctx_norm_g (256) 8 ctx_norm_b (256)
    // 9 Wkv (256,512)   10 Wout (256,256)  11 bout (256)
    const float* img          = (const float*)d_in[0];
    const float* param_tokens = (const float*)d_in[1];
    const float* Wparam       = (const float*)d_in[5];
    const float* bparam       = (const float*)d_in[6];
    const float* ctx_g        = (const float*)d_in[7];
    const float* ctx_b        = (const float*)d_in[8];
    const float* Wkv          = (const float*)d_in[9];
    const float* Wout         = (const float*)d_in[10];
    const float* bout         = (const float*)d_in[11];
    float* out = (float*)d_out;

    compute_ov_kernel<<<8, 1024>>>(param_tokens, Wparam, bparam,
                                   ctx_g, ctx_b, Wkv, Wout, bout);

    // Dependent launch with programmatic stream serialization (PDL).
    cudaLaunchConfig_t cfg = {};
    cfg.gridDim  = dim3(512, 1, 1);
    cfg.blockDim = dim3(256, 1, 1);
    cfg.dynamicSmemBytes = 0;
    cfg.stream = 0;  // same (legacy default) stream the primary used
    cudaLaunchAttribute attr[1];
    attr[0].id = cudaLaunchAttributeProgrammaticStreamSerialization;
    attr[0].val.programmaticStreamSerializationAllowed = 1;
    cfg.attrs = attr;
    cfg.numAttrs = 1;
    cudaLaunchKernelEx(&cfg, broadcast_add_kernel,
                       (const float4*)img, (float4*)out);
}

// round 15
// speedup vs baseline: 1.3433x; 1.2149x over previous
#include <cuda_runtime.h>

// d_ov[b*256 + c], 16B-aligned for float4 reads in the broadcast kernel.
__device__ __align__(16) float d_ov[8 * 256];

#define EPSF 1e-5f

// 8 blocks (one per batch) x 1024 threads.
// Thread layout: c4 = tid & 63 -> 4 consecutive channels (float4 column group),
//                sl = tid >> 6 -> one of 16 k-slices of 16.
// Each GEMV = 16 independent float4 loads per thread (one latency wave) + a
// padded shared-memory reduction over the 16 slices.
__global__ void __launch_bounds__(1024, 1)
compute_ov_kernel(const float*  __restrict__ param_tokens,  // (8,16)
                  const float*  __restrict__ Wparam,        // (16,256)
                  const float*  __restrict__ bparam,        // (256)
                  const float*  __restrict__ ctx_g,         // (256)
                  const float*  __restrict__ ctx_b,         // (256)
                  const float4* __restrict__ Wkv4,          // (256,512): row k = f4 [k*128, k*128+128)
                  const float4* __restrict__ Wout4,         // (256,256): row k = f4 [k*64, k*64+64)
                  const float4* __restrict__ bout4)         // (256) as float4
{
    // Let the dependent broadcast grid launch immediately (PDL).
    asm volatile("griddepcontrol.launch_dependents;");

    const int b   = blockIdx.x;
    const int tid = threadIdx.x;
    const int c4  = tid & 63;          // float4 column group
    const int sl  = tid >> 6;          // k-slice 0..15
    const int kb  = sl * 16;           // slice k-base

    __shared__ float  s_ln[256];
    __shared__ float  s_v[256];
    __shared__ float4 s_part[16 * 65]; // padded stride 65 to spread banks
    __shared__ float  s_red[16];

    // GEMV1 weight column-group pointer (V half). Prefetch the first 8 rows of
    // this thread's slice NOW — data-independent, lands during ctx/LN.
    const float4* wk = Wkv4 + 64 + c4;
    float4 wpre[8];
#pragma unroll
    for (int i = 0; i < 8; ++i) wpre[i] = wk[(kb + i) * 128];

    // ---- ctx[c] + LN stats (threads 0..255 only) ----
    float ctx = 0.0f;
    if (tid < 256) {
        const int c = tid;
        ctx = bparam[c];
        const float* pt = param_tokens + b * 16;
#pragma unroll
        for (int p = 0; p < 16; ++p)
            ctx = fmaf(__ldg(&pt[p]), Wparam[p * 256 + c], ctx);

        float ss = ctx, qq = ctx * ctx;
#pragma unroll
        for (int o = 16; o > 0; o >>= 1) {
            ss += __shfl_down_sync(0xffffffffu, ss, o);
            qq += __shfl_down_sync(0xffffffffu, qq, o);
        }
        const int warp = tid >> 5, lane = tid & 31;   // warps 0..7
        if (lane == 0) { s_red[warp] = ss; s_red[8 + warp] = qq; }
    }
    __syncthreads();
    if (tid < 32) {
        float ss = (tid < 8) ? s_red[tid]     : 0.0f;
        float qq = (tid < 8) ? s_red[8 + tid] : 0.0f;
#pragma unroll
        for (int o = 4; o > 0; o >>= 1) {
            ss += __shfl_down_sync(0xffffffffu, ss, o);
            qq += __shfl_down_sync(0xffffffffu, qq, o);
        }
        if (tid == 0) { s_red[0] = ss; s_red[1] = qq; }
    }
    __syncthreads();
    if (tid < 256) {
        const float mean = s_red[0] * (1.0f / 256.0f);
        const float var  = s_red[1] * (1.0f / 256.0f) - mean * mean;
        const float rinv = rsqrtf(var + EPSF);
        s_ln[tid] = fmaf((ctx - mean) * rinv, ctx_g[tid], ctx_b[tid]);
    }
    __syncthreads();

    // ---- GEMV1 slice: acc = sum_{i<16} ln[kb+i] * WkvV[kb+i, c4] ----
    {
        float4 acc = make_float4(0.f, 0.f, 0.f, 0.f);
#pragma unroll
        for (int i = 0; i < 8; ++i) {
            const float f = s_ln[kb + i];
            acc.x = fmaf(f, wpre[i].x, acc.x);
            acc.y = fmaf(f, wpre[i].y, acc.y);
            acc.z = fmaf(f, wpre[i].z, acc.z);
            acc.w = fmaf(f, wpre[i].w, acc.w);
        }
#pragma unroll
        for (int i = 8; i < 16; ++i) {
            const float  f = s_ln[kb + i];
            const float4 w = wk[(kb + i) * 128];   // front-batched, one wave
            acc.x = fmaf(f, w.x, acc.x);
            acc.y = fmaf(f, w.y, acc.y);
            acc.z = fmaf(f, w.z, acc.z);
            acc.w = fmaf(f, w.w, acc.w);
        }
        s_part[sl * 65 + c4] = acc;
    }
    __syncthreads();
    if (tid < 64) {
        float4 v = make_float4(0.f, 0.f, 0.f, 0.f);
#pragma unroll
        for (int s = 0; s < 16; ++s) {
            const float4 p = s_part[s * 65 + tid];
            v.x += p.x; v.y += p.y; v.z += p.z; v.w += p.w;
        }
        reinterpret_cast<float4*>(s_v)[tid] = v;
    }
    __syncthreads();

    // ---- GEMV2 slice: acc = sum_{i<16} v[kb+i] * Wout[kb+i, c4] ----
    {
        const float4* wo = Wout4 + c4;
        float4 acc = make_float4(0.f, 0.f, 0.f, 0.f);
#pragma unroll
        for (int i = 0; i < 16; ++i) {
            const float  f = s_v[kb + i];
            const float4 w = wo[(kb + i) * 64];    // front-batched, one wave
            acc.x = fmaf(f, w.x, acc.x);
            acc.y = fmaf(f, w.y, acc.y);
            acc.z = fmaf(f, w.z, acc.z);
            acc.w = fmaf(f, w.w, acc.w);
        }
        s_part[sl * 65 + c4] = acc;
    }
    __syncthreads();
    if (tid < 64) {
        const float4 bo = bout4[tid];
        float4 o = make_float4(bo.x, bo.y, bo.z, bo.w);
#pragma unroll
        for (int s = 0; s < 16; ++s) {
            const float4 p = s_part[s * 65 + tid];
            o.x += p.x; o.y += p.y; o.z += p.z; o.w += p.w;
        }
        reinterpret_cast<float4*>(d_ov)[b * 64 + tid] = o;
    }
}

// out[b,n,c] = img[b,n,c] + ov[b,c].
// 512 blocks x 256 threads; each thread handles 4 float4s strided by 131072.
// Launched with ProgrammaticStreamSerialization: starts while compute_ov runs,
// front-batches its img loads, then griddepcontrol.wait gates the ov reads.
__global__ void __launch_bounds__(256, 8)
broadcast_add_kernel(const float4* __restrict__ img, float4* __restrict__ out)
{
    const int t  = blockIdx.x * 256 + threadIdx.x;   // 0..131071
    const int c4 = t & 63;
    const int b0 = t >> 16;                          // 0 or 1
    const float4* ovp = reinterpret_cast<const float4*>(d_ov);

    // front-batched loads — overlap with compute_ov under PDL
    const float4 a0 = img[t];
    const float4 a1 = img[t + 131072];
    const float4 a2 = img[t + 262144];
    const float4 a3 = img[t + 393216];

    // HW wait: primary grid complete + its writes (d_ov) visible.
    asm volatile("griddepcontrol.wait;");

    const float4 o0 = ovp[(b0 + 0) * 64 + c4];
    const float4 o1 = ovp[(b0 + 2) * 64 + c4];
    const float4 o2 = ovp[(b0 + 4) * 64 + c4];
    const float4 o3 = ovp[(b0 + 6) * 64 + c4];

    out[t]          = make_float4(a0.x + o0.x, a0.y + o0.y, a0.z + o0.z, a0.w + o0.w);
    out[t + 131072] = make_float4(a1.x + o1.x, a1.y + o1.y, a1.z + o1.z, a1.w + o1.w);
    out[t + 262144] = make_float4(a2.x + o2.x, a2.y + o2.y, a2.z + o2.z, a2.w + o2.w);
    out[t + 393216] = make_float4(a3.x + o3.x, a3.y + o3.y, a3.z + o3.z, a3.w + o3.w);
}

extern "C" void kernel_launch(void* const* d_in, const int* in_sizes, int n_in,
                              void* d_out, int out_size)
{
    // metadata order:
    // 0 img_tokens (8,1024,256)  1 param_tokens (8,16)
    // 2 img_norm_g 3 img_norm_b  4 Wq            <- all dead (softmax collapse)
    // 5 Wparam (16,256)  6 bparam (256)
    // 7 ctx_norm_g (256) 8 ctx_norm_b (256)
    // 9 Wkv (256,512)   10 Wout (256,256)  11 bout (256)
    const float* img          = (const float*)d_in[0];
    const float* param_tokens = (const float*)d_in[1];
    const float* Wparam       = (const float*)d_in[5];
    const float* bparam       = (const float*)d_in[6];
    const float* ctx_g        = (const float*)d_in[7];
    const float* ctx_b        = (const float*)d_in[8];
    const float* Wkv          = (const float*)d_in[9];
    const float* Wout         = (const float*)d_in[10];
    const float* bout         = (const float*)d_in[11];
    float* out = (float*)d_out;

    compute_ov_kernel<<<8, 1024>>>(param_tokens, Wparam, bparam,
                                   ctx_g, ctx_b,
                                   (const float4*)Wkv, (const float4*)Wout,
                                   (const float4*)bout);

    // Dependent launch with programmatic stream serialization (PDL).
    cudaLaunchConfig_t cfg = {};
    cfg.gridDim  = dim3(512, 1, 1);
    cfg.blockDim = dim3(256, 1, 1);
    cfg.dynamicSmemBytes = 0;
    cfg.stream = 0;  // same (legacy default) stream the primary used
    cudaLaunchAttribute attr[1];
    attr[0].id = cudaLaunchAttributeProgrammaticStreamSerialization;
    attr[0].val.programmaticStreamSerializationAllowed = 1;
    cfg.attrs = attr;
    cfg.numAttrs = 1;
    cudaLaunchKernelEx(&cfg, broadcast_add_kernel,
                       (const float4*)img, (float4*)out);
}